// round 16
// baseline (speedup 1.0000x reference)
#include <cuda_runtime.h>
#include <cuda_bf16.h>
#include <cstdint>

#define NP   200000
#define NU   50000
#define NNZE 2000000
#define DIM  64
#define NTOT (NP*DIM)      /* 12,800,000 */
#define MSGN (NU*DIM)      /*  3,200,000 */

#define NB_U ((NU + 1023) / 1024)       /* 49  */
#define NB_P ((NP + 1023) / 1024)       /* 196 */
#define SC_BLOCKS ((NNZE + 255) / 256)  /* 7813 */
#define CVT_BLOCKS (NTOT / 4 / 256)     /* 12500 exact */
#define UP_WARPS ((NU + 3) / 4)         /* 12500: quarter-warp per row */
#define UP_BLOCKS ((UP_WARPS + 7) / 8)  /* 1563 */
#define PU_WARPS (NP / 4)               /* 50000 exact */
#define PU_BLOCKS (PU_WARPS / 8)        /* 6250 exact */

__device__ __align__(16) float g_xa[NTOT];                 // layer-1 x
__device__ __align__(16) float g_xb[NTOT];                 // layer-2 x
__device__ __align__(16) __nv_bfloat162 g_xh[NTOT / 2];    // bf16 mirror of current x
__device__ __align__(16) __nv_bfloat162 g_msgh[MSGN / 2];  // bf16 msg (gather operand)

// CSR scratch
__device__ int  g_up_ptr[NU + 1];
__device__ int  g_up_off[NU];
__device__ int2 g_up_cv[NNZE];     // packed (col, val-bits), row-grouped
__device__ int  g_pu_ptr[NP + 1];
__device__ int  g_pu_off[NP];
__device__ int2 g_pu_cv[NNZE];
__device__ int  g_bsum_u[64];
__device__ int  g_bsum_p[256];

// ---------------- threefry2x32 (exact JAX semantics) ----------------
__host__ __device__ __forceinline__ uint32_t rotl32(uint32_t x, int d) {
    return (x << d) | (x >> (32 - d));
}

__host__ __device__ __forceinline__ void tf2x32(uint32_t k0, uint32_t k1,
                                                uint32_t x0, uint32_t x1,
                                                uint32_t &o0, uint32_t &o1) {
    uint32_t ks2 = k0 ^ k1 ^ 0x1BD11BDAu;
    x0 += k0; x1 += k1;
#define TFR(r) { x0 += x1; x1 = rotl32(x1, (r)); x1 ^= x0; }
    TFR(13) TFR(15) TFR(26) TFR(6)
    x0 += k1;  x1 += ks2 + 1u;
    TFR(17) TFR(29) TFR(16) TFR(24)
    x0 += ks2; x1 += k0 + 2u;
    TFR(13) TFR(15) TFR(26) TFR(6)
    x0 += k0;  x1 += k1 + 3u;
    TFR(17) TFR(29) TFR(16) TFR(24)
    x0 += k1;  x1 += ks2 + 4u;
    TFR(13) TFR(15) TFR(26) TFR(6)
    x0 += ks2; x1 += k0 + 5u;
#undef TFR
    o0 = x0; o1 = x1;
}

// partitionable threefry draw for element e (counter (0, e)), 32-bit: out0 ^ out1
__device__ __forceinline__ uint32_t tf_bits(uint32_t k0, uint32_t k1, uint32_t e) {
    uint32_t o0, o1;
    tf2x32(k0, k1, 0u, e, o0, o1);
    return o0 ^ o1;
}

__device__ __forceinline__ float dropv(uint32_t bits, float s) {
    return (bits & 0x80000000u) ? 0.f : 2.f * s;   // keep iff MSB==0, scale 1/keep=2
}

__device__ __forceinline__ float2 bf2f(uint32_t raw) {
    return __bfloat1622float2(*reinterpret_cast<__nv_bfloat162*>(&raw));
}

__device__ __forceinline__ uint32_t f2bf(float a, float b) {
    __nv_bfloat162 h = __floats2bfloat162_rn(a, b);
    return *reinterpret_cast<uint32_t*>(&h);
}

// ---------------- CSR build ----------------
__global__ void zero_cnt_kernel() {
    int i = blockIdx.x * blockDim.x + threadIdx.x;
    if (i <= NU) g_up_ptr[i] = 0;
    if (i <= NP) g_pu_ptr[i] = 0;
}

__global__ void hist_kernel(const int* __restrict__ up_rows,
                            const int* __restrict__ pu_rows) {
    int e = blockIdx.x * blockDim.x + threadIdx.x;
    if (e >= NNZE) return;
    atomicAdd(&g_up_ptr[__ldg(up_rows + e)], 1);
    atomicAdd(&g_pu_ptr[__ldg(pu_rows + e)], 1);
}

// merged pass 1: blocks [0,NB_U) scan UP counts, [NB_U,NB_U+NB_P) scan PU counts
__global__ void scan1_kernel() {
    __shared__ int ws[32];
    int t = threadIdx.x;
    bool isU = blockIdx.x < NB_U;
    int lb = isU ? blockIdx.x : blockIdx.x - NB_U;
    int n  = isU ? NU : NP;
    const int* cnt = isU ? g_up_ptr : g_pu_ptr;
    int* excl      = isU ? g_up_off : g_pu_off;
    int* bsum      = isU ? g_bsum_u : g_bsum_p;

    int i = lb * 1024 + t;
    int v = (i < n) ? cnt[i] : 0;
    int x = v;
#pragma unroll
    for (int d = 1; d < 32; d <<= 1) {
        int u = __shfl_up_sync(~0u, x, d);
        if ((t & 31) >= d) x += u;
    }
    if ((t & 31) == 31) ws[t >> 5] = x;
    __syncthreads();
    if (t < 32) {
        int w = ws[t];
#pragma unroll
        for (int d = 1; d < 32; d <<= 1) {
            int u = __shfl_up_sync(~0u, w, d);
            if (t >= d) w += u;
        }
        ws[t] = w;
    }
    __syncthreads();
    int base = (t >= 32) ? ws[(t >> 5) - 1] : 0;
    int incl = x + base;
    if (i < n) excl[i] = incl - v;
    if (t == 1023) bsum[lb] = incl;
}

// merged pass 2: block 0 scans UP block sums, block 1 scans PU block sums
__global__ void scan2_kernel() {
    __shared__ int ws[8];
    bool isU = blockIdx.x == 0;
    int nb   = isU ? NB_U : NB_P;
    int* bsum  = isU ? g_bsum_u : g_bsum_p;
    int* ptr_n = isU ? &g_up_ptr[NU] : &g_pu_ptr[NP];

    int t = threadIdx.x;       // 256 threads
    int v = (t < nb) ? bsum[t] : 0;
    int x = v;
#pragma unroll
    for (int d = 1; d < 32; d <<= 1) {
        int u = __shfl_up_sync(~0u, x, d);
        if ((t & 31) >= d) x += u;
    }
    if ((t & 31) == 31) ws[t >> 5] = x;
    __syncthreads();
    if (t < 8) {
        int w = ws[t];
#pragma unroll
        for (int d = 1; d < 8; d <<= 1) {
            int u = __shfl_up_sync(0xffu, w, d);
            if (t >= d) w += u;
        }
        ws[t] = w;
    }
    __syncthreads();
    int base = (t >= 32) ? ws[(t >> 5) - 1] : 0;
    int incl = x + base;
    if (t < nb) bsum[t] = incl - v;
    if (t == nb - 1) *ptr_n = incl;
}

// merged pass 3: add block offset; write both ptr and off
__global__ void scan3_kernel() {
    bool isU = blockIdx.x < NB_U;
    int lb = isU ? blockIdx.x : blockIdx.x - NB_U;
    int n  = isU ? NU : NP;
    int* ptr = isU ? g_up_ptr : g_pu_ptr;
    int* off = isU ? g_up_off : g_pu_off;
    const int* bsum = isU ? g_bsum_u : g_bsum_p;

    int i = lb * 1024 + threadIdx.x;
    if (i < n) {
        int v = off[i] + bsum[lb];
        ptr[i] = v;
        off[i] = v;
    }
}

// ---------------- launch A: scatter UP entries || cvt pois -> bf16 ----------
__global__ void scatter_up_cvt_kernel(const int* __restrict__ up_rows,
                                      const int* __restrict__ up_cols,
                                      const float* __restrict__ up_vals,
                                      const float4* __restrict__ pois) {
    if (blockIdx.x < SC_BLOCKS) {
        int e = blockIdx.x * 256 + threadIdx.x;
        if (e >= NNZE) return;
        int r = __ldg(up_rows + e);
        int p = atomicAdd(&g_up_off[r], 1);
        g_up_cv[p] = make_int2(__ldg(up_cols + e), __float_as_int(__ldg(up_vals + e)));
    } else {
        int i = (blockIdx.x - SC_BLOCKS) * 256 + threadIdx.x;  // < NTOT/4 exact
        float4 v = pois[i];
        g_xh[2 * i]     = __floats2bfloat162_rn(v.x, v.y);
        g_xh[2 * i + 1] = __floats2bfloat162_rn(v.z, v.w);
    }
}

// ---------------- UP SpMM body: quarter-warp per U-row (4 rows per warp) ----
// lane = 8*q + sl; quarter q owns row w = 4*g + q.
// lane gathers uint4 (8 bf16) at positions [sl*8, sl*8+8) of the x row;
// writes one uint4 (8 bf16) of the msg row. No reductions, no tails.
__device__ __forceinline__ void spmm_up_body(int g, int lane) {
    int q = lane >> 3, sl = lane & 7;
    int w = 4 * g + q;
    if (w >= NU) return;
    int s = __ldg(g_up_ptr + w), e = __ldg(g_up_ptr + w + 1);
    float a0 = 0.f, a1 = 0.f, a2 = 0.f, a3 = 0.f;
    float a4 = 0.f, a5 = 0.f, a6 = 0.f, a7 = 0.f;
    const uint4* xbase = reinterpret_cast<const uint4*>(g_xh);
    for (int j = s; j < e; ++j) {
        int2 cv = __ldg(g_up_cv + j);            // same addr in quarter-warp
        float v = __int_as_float(cv.y);
        uint4 raw = __ldg(xbase + (size_t)cv.x * 8 + sl);
        float2 p0 = bf2f(raw.x), p1 = bf2f(raw.y), p2 = bf2f(raw.z), p3 = bf2f(raw.w);
        a0 += v * p0.x; a1 += v * p0.y;
        a2 += v * p1.x; a3 += v * p1.y;
        a4 += v * p2.x; a5 += v * p2.y;
        a6 += v * p3.x; a7 += v * p3.y;
    }
    uint4 o;
    o.x = f2bf(a0, a1); o.y = f2bf(a2, a3); o.z = f2bf(a4, a5); o.w = f2bf(a6, a7);
    reinterpret_cast<uint4*>(g_msgh)[(size_t)w * 8 + sl] = o;
}

// ---------------- launch B: UP SpMM layer 0 || scatter PU entries ----------
__global__ void up0_scatter_pu_kernel(const int* __restrict__ pu_rows,
                                      const int* __restrict__ pu_cols,
                                      const float* __restrict__ pu_vals) {
    if (blockIdx.x < UP_BLOCKS) {
        int g = (blockIdx.x * 256 + threadIdx.x) >> 5;
        if (g < UP_WARPS) spmm_up_body(g, threadIdx.x & 31);
    } else {
        int e = (blockIdx.x - UP_BLOCKS) * 256 + threadIdx.x;
        if (e >= NNZE) return;
        int r = __ldg(pu_rows + e);
        int p = atomicAdd(&g_pu_off[r], 1);
        g_pu_cv[p] = make_int2(__ldg(pu_cols + e), __float_as_int(__ldg(pu_vals + e)));
    }
}

// plain UP SpMM for layers 1, 2
__global__ void spmm_up_kernel() {
    int g = (blockIdx.x * 256 + threadIdx.x) >> 5;
    if (g < UP_WARPS) spmm_up_body(g, threadIdx.x & 31);
}

// ---------------- PU SpMM fused: quarter-warp per row (4 independent rows) --
// lane = 8*q + sl; quarter q owns row w = 4*g + q.
// lane gathers uint4 (8 bf16) at positions [sl*8, sl*8+8) of the msg row.
// Epilogue: 2x float4 on elements [w*64 + sl*8, +8); threefry inline (exact).
__global__ void spmm_pu_fused_kernel(const float* __restrict__ x_in,
                                     float* __restrict__ x_out,
                                     const float* __restrict__ pois_in,
                                     const float* __restrict__ x1_in,
                                     uint32_t k0, uint32_t k1, int last,
                                     float* __restrict__ out) {
    int g = (blockIdx.x * 256 + threadIdx.x) >> 5;       // < NP/4 exact
    int lane = threadIdx.x & 31;
    int q = lane >> 3, sl = lane & 7;
    int w = 4 * g + q;                                   // this quarter's row
    int s = __ldg(g_pu_ptr + w), e = __ldg(g_pu_ptr + w + 1);
    float a0 = 0.f, a1 = 0.f, a2 = 0.f, a3 = 0.f;
    float a4 = 0.f, a5 = 0.f, a6 = 0.f, a7 = 0.f;
    const uint4* mbase = reinterpret_cast<const uint4*>(g_msgh);
    for (int j = s; j < e; ++j) {
        int2 cv = __ldg(g_pu_cv + j);            // same addr in quarter-warp
        float v = __int_as_float(cv.y);
        uint4 raw = __ldg(mbase + (size_t)cv.x * 8 + sl);
        float2 p0 = bf2f(raw.x), p1 = bf2f(raw.y), p2 = bf2f(raw.z), p3 = bf2f(raw.w);
        a0 += v * p0.x; a1 += v * p0.y;
        a2 += v * p1.x; a3 += v * p1.y;
        a4 += v * p2.x; a5 += v * p2.y;
        a6 += v * p3.x; a7 += v * p3.y;
    }

    size_t idx = (size_t)w * DIM + sl * 8;
    uint32_t e0 = (uint32_t)idx;
    uint32_t b0 = tf_bits(k0, k1, e0);
    uint32_t b1 = tf_bits(k0, k1, e0 + 1u);
    uint32_t b2 = tf_bits(k0, k1, e0 + 2u);
    uint32_t b3 = tf_bits(k0, k1, e0 + 3u);
    uint32_t b4 = tf_bits(k0, k1, e0 + 4u);
    uint32_t b5 = tf_bits(k0, k1, e0 + 5u);
    uint32_t b6 = tf_bits(k0, k1, e0 + 6u);
    uint32_t b7 = tf_bits(k0, k1, e0 + 7u);

    float4 xv0 = *reinterpret_cast<const float4*>(x_in + idx);
    float4 xv1 = *reinterpret_cast<const float4*>(x_in + idx + 4);
    float n0 = dropv(b0, a0 + xv0.x);
    float n1 = dropv(b1, a1 + xv0.y);
    float n2 = dropv(b2, a2 + xv0.z);
    float n3 = dropv(b3, a3 + xv0.w);
    float n4 = dropv(b4, a4 + xv1.x);
    float n5 = dropv(b5, a5 + xv1.y);
    float n6 = dropv(b6, a6 + xv1.z);
    float n7 = dropv(b7, a7 + xv1.w);

    if (last) {
        float4 pv0 = *reinterpret_cast<const float4*>(pois_in + idx);
        float4 pv1 = *reinterpret_cast<const float4*>(pois_in + idx + 4);
        float4 x10 = *reinterpret_cast<const float4*>(x1_in + idx);
        float4 x11 = *reinterpret_cast<const float4*>(x1_in + idx + 4);
        *reinterpret_cast<float4*>(out + idx) =
            make_float4((pv0.x + x10.x + xv0.x + n0) * 0.25f,
                        (pv0.y + x10.y + xv0.y + n1) * 0.25f,
                        (pv0.z + x10.z + xv0.z + n2) * 0.25f,
                        (pv0.w + x10.w + xv0.w + n3) * 0.25f);
        *reinterpret_cast<float4*>(out + idx + 4) =
            make_float4((pv1.x + x11.x + xv1.x + n4) * 0.25f,
                        (pv1.y + x11.y + xv1.y + n5) * 0.25f,
                        (pv1.z + x11.z + xv1.z + n6) * 0.25f,
                        (pv1.w + x11.w + xv1.w + n7) * 0.25f);
    } else {
        *reinterpret_cast<float4*>(x_out + idx)     = make_float4(n0, n1, n2, n3);
        *reinterpret_cast<float4*>(x_out + idx + 4) = make_float4(n4, n5, n6, n7);
        uint4 o;
        o.x = f2bf(n0, n1); o.y = f2bf(n2, n3); o.z = f2bf(n4, n5); o.w = f2bf(n6, n7);
        reinterpret_cast<uint4*>(g_xh)[idx / 8] = o;
    }
}

// ---------------- launch ----------------
// Inputs in dict/insertion order:
//   d_in[0]=pois_embs, d_in[1]=up_rows, d_in[2]=up_cols, d_in[3]=up_vals,
//   d_in[4]=pu_rows,   d_in[5]=pu_cols, d_in[6]=pu_vals
extern "C" void kernel_launch(void* const* d_in, const int* in_sizes, int n_in,
                              void* d_out, int out_size) {
    const float* pois    = (const float*)d_in[0];
    const int*   up_rows = (const int*)  d_in[1];
    const int*   up_cols = (const int*)  d_in[2];
    const float* up_vals = (const float*)d_in[3];
    const int*   pu_rows = (const int*)  d_in[4];
    const int*   pu_cols = (const int*)  d_in[5];
    const float* pu_vals = (const float*)d_in[6];
    float* out = (float*)d_out;

    float *pxa, *pxb;
    cudaGetSymbolAddress((void**)&pxa, g_xa);
    cudaGetSymbolAddress((void**)&pxb, g_xb);

    // per-layer dropout keys: fold_in(key(42), l) = threefry((0,42),(0,l))
    uint32_t lk0[3], lk1[3];
    for (int l = 0; l < 3; ++l)
        tf2x32(0u, 42u, 0u, (uint32_t)l, lk0[l], lk1[l]);

    const int B = 256;

    // ---- CSR build (once per call, reused by all 3 layers) ----
    zero_cnt_kernel<<<(NP + 1 + B - 1) / B, B>>>();
    hist_kernel<<<SC_BLOCKS, B>>>(up_rows, pu_rows);
    scan1_kernel<<<NB_U + NB_P, 1024>>>();
    scan2_kernel<<<2, 256>>>();
    scan3_kernel<<<NB_U + NB_P, 1024>>>();

    // launch A: scatter UP || cvt pois->bf16
    scatter_up_cvt_kernel<<<SC_BLOCKS + CVT_BLOCKS, B>>>(up_rows, up_cols, up_vals,
                                                         (const float4*)pois);
    // launch B: UP SpMM layer 0 || scatter PU
    up0_scatter_pu_kernel<<<UP_BLOCKS + SC_BLOCKS, B>>>(pu_rows, pu_cols, pu_vals);

    // ---- layers (lazy acc: mean folded at last layer) ----
    // layer 0 PU: x_in = pois -> x1 in g_xa
    spmm_pu_fused_kernel<<<PU_BLOCKS, B>>>(pois, pxa, nullptr, nullptr,
                                           lk0[0], lk1[0], 0, out);
    // layer 1
    spmm_up_kernel<<<UP_BLOCKS, B>>>();
    spmm_pu_fused_kernel<<<PU_BLOCKS, B>>>(pxa, pxb, nullptr, nullptr,
                                           lk0[1], lk1[1], 0, out);
    // layer 2: out = 0.25*(pois + x1 + x2 + x3)
    spmm_up_kernel<<<UP_BLOCKS, B>>>();
    spmm_pu_fused_kernel<<<PU_BLOCKS, B>>>(pxb, nullptr, pois, pxa,
                                           lk0[2], lk1[2], 1, out);
}

// round 17
// speedup vs baseline: 1.0311x; 1.0311x over previous
#include <cuda_runtime.h>
#include <cuda_bf16.h>
#include <cstdint>

#define NP   200000
#define NU   50000
#define NNZE 2000000
#define DIM  64
#define NTOT (NP*DIM)      /* 12,800,000 */
#define MSGN (NU*DIM)      /*  3,200,000 */

#define NB_U ((NU + 1023) / 1024)       /* 49  */
#define NB_P ((NP + 1023) / 1024)       /* 196 */
#define SC4_BLOCKS ((NNZE / 4 + 255) / 256) /* 1954: int4 build kernels */
#define CVT_BLOCKS (NTOT / 4 / 256)     /* 12500 exact */
#define UP_BLOCKS (NU * 16 / 256)       /* 3125 exact: half-warp per row */
#define PU_BLOCKS (NP * 16 / 256)       /* 12500 exact: half-warp per row */

__device__ __align__(16) float g_xa[NTOT];                 // layer-1 x
__device__ __align__(16) float g_xb[NTOT];                 // layer-2 x
__device__ __align__(16) __nv_bfloat162 g_xh[NTOT / 2];    // bf16 mirror of current x
__device__ __align__(16) __nv_bfloat162 g_msgh[MSGN / 2];  // bf16 msg (gather operand)

// CSR scratch
__device__ int  g_up_ptr[NU + 1];
__device__ int  g_up_off[NU];
__device__ int2 g_up_cv[NNZE];     // packed (col, val-bits), row-grouped
__device__ int  g_pu_ptr[NP + 1];
__device__ int  g_pu_off[NP];
__device__ int2 g_pu_cv[NNZE];
__device__ int  g_bsum_u[64];
__device__ int  g_bsum_p[256];

// ---------------- threefry2x32 (exact JAX semantics) ----------------
__host__ __device__ __forceinline__ uint32_t rotl32(uint32_t x, int d) {
    return (x << d) | (x >> (32 - d));
}

__host__ __device__ __forceinline__ void tf2x32(uint32_t k0, uint32_t k1,
                                                uint32_t x0, uint32_t x1,
                                                uint32_t &o0, uint32_t &o1) {
    uint32_t ks2 = k0 ^ k1 ^ 0x1BD11BDAu;
    x0 += k0; x1 += k1;
#define TFR(r) { x0 += x1; x1 = rotl32(x1, (r)); x1 ^= x0; }
    TFR(13) TFR(15) TFR(26) TFR(6)
    x0 += k1;  x1 += ks2 + 1u;
    TFR(17) TFR(29) TFR(16) TFR(24)
    x0 += ks2; x1 += k0 + 2u;
    TFR(13) TFR(15) TFR(26) TFR(6)
    x0 += k0;  x1 += k1 + 3u;
    TFR(17) TFR(29) TFR(16) TFR(24)
    x0 += k1;  x1 += ks2 + 4u;
    TFR(13) TFR(15) TFR(26) TFR(6)
    x0 += ks2; x1 += k0 + 5u;
#undef TFR
    o0 = x0; o1 = x1;
}

// partitionable threefry draw for element e (counter (0, e)), 32-bit: out0 ^ out1
__device__ __forceinline__ uint32_t tf_bits(uint32_t k0, uint32_t k1, uint32_t e) {
    uint32_t o0, o1;
    tf2x32(k0, k1, 0u, e, o0, o1);
    return o0 ^ o1;
}

__device__ __forceinline__ float dropv(uint32_t bits, float s) {
    return (bits & 0x80000000u) ? 0.f : 2.f * s;   // keep iff MSB==0, scale 1/keep=2
}

__device__ __forceinline__ float2 bf2f(uint32_t raw) {
    return __bfloat1622float2(*reinterpret_cast<__nv_bfloat162*>(&raw));
}

// ---------------- CSR build ----------------
__global__ void zero_cnt_kernel() {
    int i = blockIdx.x * blockDim.x + threadIdx.x;
    if (i <= NU) g_up_ptr[i] = 0;
    if (i <= NP) g_pu_ptr[i] = 0;
}

// int4-vectorized histogram: 4 nnz per thread, both matrices
__global__ void hist_kernel(const int4* __restrict__ up_rows,
                            const int4* __restrict__ pu_rows) {
    int e = blockIdx.x * blockDim.x + threadIdx.x;
    if (e >= NNZE / 4) return;
    int4 a = __ldg(up_rows + e);
    atomicAdd(&g_up_ptr[a.x], 1); atomicAdd(&g_up_ptr[a.y], 1);
    atomicAdd(&g_up_ptr[a.z], 1); atomicAdd(&g_up_ptr[a.w], 1);
    int4 b = __ldg(pu_rows + e);
    atomicAdd(&g_pu_ptr[b.x], 1); atomicAdd(&g_pu_ptr[b.y], 1);
    atomicAdd(&g_pu_ptr[b.z], 1); atomicAdd(&g_pu_ptr[b.w], 1);
}

// merged pass 1: blocks [0,NB_U) scan UP counts, [NB_U,NB_U+NB_P) scan PU counts
__global__ void scan1_kernel() {
    __shared__ int ws[32];
    int t = threadIdx.x;
    bool isU = blockIdx.x < NB_U;
    int lb = isU ? blockIdx.x : blockIdx.x - NB_U;
    int n  = isU ? NU : NP;
    const int* cnt = isU ? g_up_ptr : g_pu_ptr;
    int* excl      = isU ? g_up_off : g_pu_off;
    int* bsum      = isU ? g_bsum_u : g_bsum_p;

    int i = lb * 1024 + t;
    int v = (i < n) ? cnt[i] : 0;
    int x = v;
#pragma unroll
    for (int d = 1; d < 32; d <<= 1) {
        int u = __shfl_up_sync(~0u, x, d);
        if ((t & 31) >= d) x += u;
    }
    if ((t & 31) == 31) ws[t >> 5] = x;
    __syncthreads();
    if (t < 32) {
        int w = ws[t];
#pragma unroll
        for (int d = 1; d < 32; d <<= 1) {
            int u = __shfl_up_sync(~0u, w, d);
            if (t >= d) w += u;
        }
        ws[t] = w;
    }
    __syncthreads();
    int base = (t >= 32) ? ws[(t >> 5) - 1] : 0;
    int incl = x + base;
    if (i < n) excl[i] = incl - v;
    if (t == 1023) bsum[lb] = incl;
}

// merged pass 2: block 0 scans UP block sums, block 1 scans PU block sums
__global__ void scan2_kernel() {
    __shared__ int ws[8];
    bool isU = blockIdx.x == 0;
    int nb   = isU ? NB_U : NB_P;
    int* bsum  = isU ? g_bsum_u : g_bsum_p;
    int* ptr_n = isU ? &g_up_ptr[NU] : &g_pu_ptr[NP];

    int t = threadIdx.x;       // 256 threads
    int v = (t < nb) ? bsum[t] : 0;
    int x = v;
#pragma unroll
    for (int d = 1; d < 32; d <<= 1) {
        int u = __shfl_up_sync(~0u, x, d);
        if ((t & 31) >= d) x += u;
    }
    if ((t & 31) == 31) ws[t >> 5] = x;
    __syncthreads();
    if (t < 8) {
        int w = ws[t];
#pragma unroll
        for (int d = 1; d < 8; d <<= 1) {
            int u = __shfl_up_sync(0xffu, w, d);
            if (t >= d) w += u;
        }
        ws[t] = w;
    }
    __syncthreads();
    int base = (t >= 32) ? ws[(t >> 5) - 1] : 0;
    int incl = x + base;
    if (t < nb) bsum[t] = incl - v;
    if (t == nb - 1) *ptr_n = incl;
}

// merged pass 3: add block offset; write both ptr and off
__global__ void scan3_kernel() {
    bool isU = blockIdx.x < NB_U;
    int lb = isU ? blockIdx.x : blockIdx.x - NB_U;
    int n  = isU ? NU : NP;
    int* ptr = isU ? g_up_ptr : g_pu_ptr;
    int* off = isU ? g_up_off : g_pu_off;
    const int* bsum = isU ? g_bsum_u : g_bsum_p;

    int i = lb * 1024 + threadIdx.x;
    if (i < n) {
        int v = off[i] + bsum[lb];
        ptr[i] = v;
        off[i] = v;
    }
}

// ---------------- launch A: scatter UP (int4) || cvt pois -> bf16 ----------
__global__ void scatter_up_cvt_kernel(const int4* __restrict__ up_rows,
                                      const int4* __restrict__ up_cols,
                                      const float4* __restrict__ up_vals,
                                      const float4* __restrict__ pois) {
    if (blockIdx.x < SC4_BLOCKS) {
        int e = blockIdx.x * 256 + threadIdx.x;
        if (e >= NNZE / 4) return;
        int4 r = __ldg(up_rows + e);
        int4 c = __ldg(up_cols + e);
        float4 v = __ldg(up_vals + e);
        g_up_cv[atomicAdd(&g_up_off[r.x], 1)] = make_int2(c.x, __float_as_int(v.x));
        g_up_cv[atomicAdd(&g_up_off[r.y], 1)] = make_int2(c.y, __float_as_int(v.y));
        g_up_cv[atomicAdd(&g_up_off[r.z], 1)] = make_int2(c.z, __float_as_int(v.z));
        g_up_cv[atomicAdd(&g_up_off[r.w], 1)] = make_int2(c.w, __float_as_int(v.w));
    } else {
        int i = (blockIdx.x - SC4_BLOCKS) * 256 + threadIdx.x;  // < NTOT/4 exact
        float4 v = pois[i];
        g_xh[2 * i]     = __floats2bfloat162_rn(v.x, v.y);
        g_xh[2 * i + 1] = __floats2bfloat162_rn(v.z, v.w);
    }
}

// ---------------- UP SpMM body: half-warp per U-row (two rows per warp) -----
// lane = 16*h + sl; half-warp h owns row w = 2*g + h.
// lane gathers uint2 (4 bf16) at positions [sl*4, sl*4+4) of the x row;
// writes one uint2 (4 bf16) of the msg row. No reductions, no tails.
__device__ __forceinline__ void spmm_up_body(int g, int lane) {
    int h = lane >> 4, sl = lane & 15;
    int w = 2 * g + h;                                   // < NU
    int s = __ldg(g_up_ptr + w), e = __ldg(g_up_ptr + w + 1);
    float a0 = 0.f, a1 = 0.f, a2 = 0.f, a3 = 0.f;
    const uint2* xbase = reinterpret_cast<const uint2*>(g_xh);
    for (int j = s; j < e; ++j) {
        int2 cv = __ldg(g_up_cv + j);                // same addr in half-warp: broadcast
        float v = __int_as_float(cv.y);
        uint2 raw = __ldg(xbase + (size_t)cv.x * 16 + sl);
        float2 p0 = bf2f(raw.x), p1 = bf2f(raw.y);
        a0 += v * p0.x; a1 += v * p0.y;
        a2 += v * p1.x; a3 += v * p1.y;
    }
    uint2 o;
    __nv_bfloat162 o0 = __floats2bfloat162_rn(a0, a1);
    __nv_bfloat162 o1 = __floats2bfloat162_rn(a2, a3);
    o.x = *reinterpret_cast<uint32_t*>(&o0);
    o.y = *reinterpret_cast<uint32_t*>(&o1);
    reinterpret_cast<uint2*>(g_msgh)[(size_t)w * 16 + sl] = o;
}

// ---------------- launch B: UP SpMM layer 0 || scatter PU (int4) ----------
__global__ void up0_scatter_pu_kernel(const int4* __restrict__ pu_rows,
                                      const int4* __restrict__ pu_cols,
                                      const float4* __restrict__ pu_vals) {
    if (blockIdx.x < UP_BLOCKS) {
        int g = (blockIdx.x * 256 + threadIdx.x) >> 5;   // < NU/2 exact
        spmm_up_body(g, threadIdx.x & 31);
    } else {
        int e = (blockIdx.x - UP_BLOCKS) * 256 + threadIdx.x;
        if (e >= NNZE / 4) return;
        int4 r = __ldg(pu_rows + e);
        int4 c = __ldg(pu_cols + e);
        float4 v = __ldg(pu_vals + e);
        g_pu_cv[atomicAdd(&g_pu_off[r.x], 1)] = make_int2(c.x, __float_as_int(v.x));
        g_pu_cv[atomicAdd(&g_pu_off[r.y], 1)] = make_int2(c.y, __float_as_int(v.y));
        g_pu_cv[atomicAdd(&g_pu_off[r.z], 1)] = make_int2(c.z, __float_as_int(v.z));
        g_pu_cv[atomicAdd(&g_pu_off[r.w], 1)] = make_int2(c.w, __float_as_int(v.w));
    }
}

// plain UP SpMM for layers 1, 2
__global__ void spmm_up_kernel() {
    int g = (blockIdx.x * 256 + threadIdx.x) >> 5;       // < NU/2 exact
    spmm_up_body(g, threadIdx.x & 31);
}

// ---------------- PU SpMM fused: half-warp per row (two independent rows) ---
// lane = 16*h + sl; half-warp h owns row w = 2*g + h (g = global half-pair id).
// lane gathers uint2 (4 bf16) at positions [sl*4, sl*4+4) of the msg row.
// Epilogue: float4 on elements [w*64 + sl*4, +4); threefry inline (exact).
__global__ void spmm_pu_fused_kernel(const float* __restrict__ x_in,
                                     float* __restrict__ x_out,
                                     const float* __restrict__ pois_in,
                                     const float* __restrict__ x1_in,
                                     uint32_t k0, uint32_t k1, int last,
                                     float* __restrict__ out) {
    int g = (blockIdx.x * 256 + threadIdx.x) >> 5;       // < NP/2 exact
    int lane = threadIdx.x & 31;
    int h = lane >> 4, sl = lane & 15;
    int w = 2 * g + h;                                   // this half-warp's row
    int s = __ldg(g_pu_ptr + w), e = __ldg(g_pu_ptr + w + 1);
    float a0 = 0.f, a1 = 0.f, a2 = 0.f, a3 = 0.f;
    const uint2* mbase = reinterpret_cast<const uint2*>(g_msgh);
    for (int j = s; j < e; ++j) {
        int2 cv = __ldg(g_pu_cv + j);                // same addr in half-warp: broadcast
        float v = __int_as_float(cv.y);
        uint2 raw = __ldg(mbase + (size_t)cv.x * 16 + sl);
        float2 p0 = bf2f(raw.x), p1 = bf2f(raw.y);
        a0 += v * p0.x; a1 += v * p0.y;
        a2 += v * p1.x; a3 += v * p1.y;
    }

    size_t idx = (size_t)w * DIM + sl * 4;
    uint32_t e0 = (uint32_t)idx;
    uint32_t b0 = tf_bits(k0, k1, e0);
    uint32_t b1 = tf_bits(k0, k1, e0 + 1u);
    uint32_t b2 = tf_bits(k0, k1, e0 + 2u);
    uint32_t b3 = tf_bits(k0, k1, e0 + 3u);

    float4 xv = *reinterpret_cast<const float4*>(x_in + idx);
    float n0 = dropv(b0, a0 + xv.x);
    float n1 = dropv(b1, a1 + xv.y);
    float n2 = dropv(b2, a2 + xv.z);
    float n3 = dropv(b3, a3 + xv.w);

    if (last) {
        float4 pv = *reinterpret_cast<const float4*>(pois_in + idx);
        float4 x1 = *reinterpret_cast<const float4*>(x1_in + idx);
        *reinterpret_cast<float4*>(out + idx) =
            make_float4((pv.x + x1.x + xv.x + n0) * 0.25f,
                        (pv.y + x1.y + xv.y + n1) * 0.25f,
                        (pv.z + x1.z + xv.z + n2) * 0.25f,
                        (pv.w + x1.w + xv.w + n3) * 0.25f);
    } else {
        *reinterpret_cast<float4*>(x_out + idx) = make_float4(n0, n1, n2, n3);
        g_xh[idx / 2]     = __floats2bfloat162_rn(n0, n1);
        g_xh[idx / 2 + 1] = __floats2bfloat162_rn(n2, n3);
    }
}

// ---------------- launch ----------------
// Inputs in dict/insertion order:
//   d_in[0]=pois_embs, d_in[1]=up_rows, d_in[2]=up_cols, d_in[3]=up_vals,
//   d_in[4]=pu_rows,   d_in[5]=pu_cols, d_in[6]=pu_vals
extern "C" void kernel_launch(void* const* d_in, const int* in_sizes, int n_in,
                              void* d_out, int out_size) {
    const float* pois    = (const float*)d_in[0];
    const int*   up_rows = (const int*)  d_in[1];
    const int*   up_cols = (const int*)  d_in[2];
    const float* up_vals = (const float*)d_in[3];
    const int*   pu_rows = (const int*)  d_in[4];
    const int*   pu_cols = (const int*)  d_in[5];
    const float* pu_vals = (const float*)d_in[6];
    float* out = (float*)d_out;

    float *pxa, *pxb;
    cudaGetSymbolAddress((void**)&pxa, g_xa);
    cudaGetSymbolAddress((void**)&pxb, g_xb);

    // per-layer dropout keys: fold_in(key(42), l) = threefry((0,42),(0,l))
    uint32_t lk0[3], lk1[3];
    for (int l = 0; l < 3; ++l)
        tf2x32(0u, 42u, 0u, (uint32_t)l, lk0[l], lk1[l]);

    const int B = 256;

    // ---- CSR build (once per call, reused by all 3 layers) ----
    zero_cnt_kernel<<<(NP + 1 + B - 1) / B, B>>>();
    hist_kernel<<<SC4_BLOCKS, B>>>((const int4*)up_rows, (const int4*)pu_rows);
    scan1_kernel<<<NB_U + NB_P, 1024>>>();
    scan2_kernel<<<2, 256>>>();
    scan3_kernel<<<NB_U + NB_P, 1024>>>();

    // launch A: scatter UP (int4) || cvt pois->bf16
    scatter_up_cvt_kernel<<<SC4_BLOCKS + CVT_BLOCKS, B>>>(
        (const int4*)up_rows, (const int4*)up_cols, (const float4*)up_vals,
        (const float4*)pois);
    // launch B: UP SpMM layer 0 || scatter PU (int4)
    up0_scatter_pu_kernel<<<UP_BLOCKS + SC4_BLOCKS, B>>>(
        (const int4*)pu_rows, (const int4*)pu_cols, (const float4*)pu_vals);

    // ---- layers (lazy acc: mean folded at last layer) ----
    // layer 0 PU: x_in = pois -> x1 in g_xa
    spmm_pu_fused_kernel<<<PU_BLOCKS, B>>>(pois, pxa, nullptr, nullptr,
                                           lk0[0], lk1[0], 0, out);
    // layer 1
    spmm_up_kernel<<<UP_BLOCKS, B>>>();
    spmm_pu_fused_kernel<<<PU_BLOCKS, B>>>(pxa, pxb, nullptr, nullptr,
                                           lk0[1], lk1[1], 0, out);
    // layer 2: out = 0.25*(pois + x1 + x2 + x3)
    spmm_up_kernel<<<UP_BLOCKS, B>>>();
    spmm_pu_fused_kernel<<<PU_BLOCKS, B>>>(pxb, nullptr, pois, pxa,
                                           lk0[2], lk1[2], 1, out);
}